// round 12
// baseline (speedup 1.0000x reference)
#include <cuda_runtime.h>
#include <cuda_bf16.h>
#include <cstdint>

#define Bn 8
#define Cn 128
#define Hn 64
#define Wn 64
#define NPIX (Bn*Hn*Wn)          // 32768
#define COUT 128

#define RWB   272                // padded row bytes (128 bf16 = 256B + 16B pad)
#define WHALF (128*RWB)          // 34816: one hi (or lo) block
#define WTAP  (2*WHALF)          // 69632: per-tap image (hi + lo)

// ---- scratch (allocation-free: __device__ globals) ----
__device__ __align__(16)   float g_xt[NPIX*Cn];        // NHWC copy of x (16 MB)
__device__ __align__(16)   float g_wofft[9*4*Cn];      // w_off transposed: [tap][oc][c]
__device__ __align__(16)   float g_off[NPIX*4];        // per-pixel {off0, off1, s1, s2}
__device__ __align__(1024) unsigned char g_wsplit[9*WTAP];  // per-tap bf16 hi/lo weight images

// ===========================================================================
// PTX helpers — baseline sm_80 features only (compile on plain sm_103)
// ===========================================================================
__device__ __forceinline__ uint32_t smem_u32(const void* p) {
    uint32_t a;
    asm("{ .reg .u64 t; cvta.to.shared.u64 t, %1; cvt.u32.u64 %0, t; }" : "=r"(a) : "l"(p));
    return a;
}
__device__ __forceinline__ void cp_async16(uint32_t sdst, const void* gsrc) {
    asm volatile("cp.async.cg.shared.global [%0], [%1], 16;" :: "r"(sdst), "l"(gsrc));
}
#define CP_COMMIT() asm volatile("cp.async.commit_group;")
#define CP_WAIT0()  asm volatile("cp.async.wait_group 0;" ::: "memory")

#define BAR_SYNC(id,cnt)   asm volatile("bar.sync %0, %1;"   :: "r"(id), "r"(cnt) : "memory")
#define BAR_ARRIVE(id,cnt) asm volatile("bar.arrive %0, %1;" :: "r"(id), "r"(cnt) : "memory")

#define LDSM4(r0,r1,r2,r3,a) \
    asm volatile("ldmatrix.sync.aligned.m8n8.x4.shared.b16 {%0,%1,%2,%3}, [%4];" \
                 : "=r"(r0),"=r"(r1),"=r"(r2),"=r"(r3) : "r"(a))

#define MMA16816(c,a0,a1,a2,a3,b0,b1) \
    asm volatile("mma.sync.aligned.m16n8k16.row.col.f32.bf16.bf16.f32 " \
                 "{%0,%1,%2,%3}, {%4,%5,%6,%7}, {%8,%9}, {%0,%1,%2,%3};" \
                 : "+f"((c)[0]),"+f"((c)[1]),"+f"((c)[2]),"+f"((c)[3]) \
                 : "r"(a0),"r"(a1),"r"(a2),"r"(a3),"r"(b0),"r"(b1))

// named barrier ids
#define NB_FULL0  1
#define NB_FULL1  2
#define NB_EMPTY0 3
#define NB_EMPTY1 4
#define NB_CONS   5

#define NTHR   640
#define NCONS  512

// ===========================================================================
// Kernel 1: prep — w -> bf16 hi/lo split in padded [o][c] rows; w_off transpose
// ===========================================================================
__global__ void prep_kernel(const float* __restrict__ w, const float* __restrict__ w_off) {
    int tid = blockIdx.x * 256 + threadIdx.x;
    if (tid < 9*Cn*COUT) {
        int k = tid / (Cn*COUT);
        int r = tid % (Cn*COUT);
        int o = r >> 7;
        int c = r & 127;
        float v = w[(o*Cn + c)*9 + k];
        __nv_bfloat16 hi = __float2bfloat16(v);
        __nv_bfloat16 lo = __float2bfloat16(v - __bfloat162float(hi));
        unsigned char* base = g_wsplit + k*WTAP;
        *(__nv_bfloat16*)(base + o*RWB + c*2)         = hi;
        *(__nv_bfloat16*)(base + WHALF + o*RWB + c*2) = lo;
    }
    if (tid < 9*4*Cn) {
        int tap = tid / (4*Cn);
        int r   = tid % (4*Cn);
        int oc  = r / Cn;
        int c   = r % Cn;
        g_wofft[tid] = w_off[(oc*Cn + c)*9 + tap];
    }
}

// ===========================================================================
// Kernel 2: NCHW -> NHWC transpose of x
// ===========================================================================
__global__ void transpose_kernel(const float* __restrict__ x) {
    __shared__ float tile[32][33];
    int bh = blockIdx.z;
    int b = bh >> 6, h = bh & 63;
    int c0 = blockIdx.y * 32;
    int w0 = blockIdx.x * 32;
    int tx = threadIdx.x, ty = threadIdx.y;
    #pragma unroll
    for (int i = 0; i < 32; i += 8)
        tile[ty + i][tx] = x[((b*Cn + c0 + ty + i)*Hn + h)*Wn + w0 + tx];
    __syncthreads();
    #pragma unroll
    for (int i = 0; i < 32; i += 8)
        g_xt[((bh*Wn) + w0 + ty + i)*Cn + c0 + tx] = tile[tx][ty + i];
}

// ===========================================================================
// Kernel 3: offset conv -> per-pixel params {off0, off1, s1, s2}
// ===========================================================================
__global__ __launch_bounds__(256) void offset_kernel(const float* __restrict__ b_off) {
    __shared__ float sw[9*4*Cn];
    int tid = threadIdx.x;
    for (int i = tid; i < 9*4*Cn; i += 256) sw[i] = g_wofft[i];
    __syncthreads();

    int warp = tid >> 5, lane = tid & 31;
    int pix = blockIdx.x * 8 + warp;
    int b   = pix >> 12;
    int rem = pix & 4095;
    int h   = rem >> 6, w = rem & 63;

    float a0 = 0.f, a1 = 0.f, a2 = 0.f, a3 = 0.f;
    const float4* xt4 = (const float4*)g_xt;

    #pragma unroll
    for (int tap = 0; tap < 9; tap++) {
        int dy = tap/3 - 1, dx = tap%3 - 1;
        int yy = h + dy, xx = w + dx;
        if (yy < 0 || yy >= Hn || xx < 0 || xx >= Wn) continue;
        float4 v = xt4[((b*Hn + yy)*Wn + xx)*(Cn/4) + lane];
        const float4* wv = (const float4*)&sw[tap*4*Cn];
        float4 w0v = wv[0*32 + lane];
        float4 w1v = wv[1*32 + lane];
        float4 w2v = wv[2*32 + lane];
        float4 w3v = wv[3*32 + lane];
        a0 += v.x*w0v.x + v.y*w0v.y + v.z*w0v.z + v.w*w0v.w;
        a1 += v.x*w1v.x + v.y*w1v.y + v.z*w1v.z + v.w*w1v.w;
        a2 += v.x*w2v.x + v.y*w2v.y + v.z*w2v.z + v.w*w2v.w;
        a3 += v.x*w3v.x + v.y*w3v.y + v.z*w3v.z + v.w*w3v.w;
    }
    #pragma unroll
    for (int s = 16; s; s >>= 1) {
        a0 += __shfl_xor_sync(0xffffffffu, a0, s);
        a1 += __shfl_xor_sync(0xffffffffu, a1, s);
        a2 += __shfl_xor_sync(0xffffffffu, a2, s);
        a3 += __shfl_xor_sync(0xffffffffu, a3, s);
    }
    if (lane == 0) {
        float4 r;
        r.x = a0 + b_off[0];
        r.y = a1 + b_off[1];
        r.z = fmaxf(a2 + b_off[2], 0.f) + 1.f;
        r.w = fmaxf(a3 + b_off[3], 0.f) + 1.f;
        ((float4*)g_off)[pix] = r;
    }
}

// ===========================================================================
// Kernel 4: warp-specialized HMMA, 640 threads.
// Warps 0-15 consumers (warp tile M16 x N64: mg=wid&7, ng=wid>>3),
// warps 16-19 producers (coalesced sampling, 8 lanes per pixel).
// A double-buffered; W single-buffered, restaged by consumers.
// smem: W 69632 | A0 69632 | A1 69632 = 208,896 B
// ===========================================================================
#define SMEM_W  0
#define SMEM_A0 69632
#define SMEM_A1 139264
#define SMEM_BYTES 208896

__global__ __launch_bounds__(NTHR, 1) void main_ws_kernel(const float* __restrict__ bias,
                                                          float* __restrict__ out) {
    extern __shared__ char smem[];
    uint32_t sb = smem_u32(smem);
    int tid  = threadIdx.x;
    int wid  = tid >> 5;
    int lane = tid & 31;
    int blk  = blockIdx.x;              // 256 blocks: (b, row-pair)
    int b    = blk >> 5;
    int h0   = (blk & 31) << 1;

    if (wid < 16) {
        // ===================== CONSUMER =====================
        // preload W tap 0 (4352 float4s over 512 threads)
        {
            const unsigned char* src = g_wsplit;
            #pragma unroll
            for (int i = 0; i < 9; i++) {
                int idx = tid + i*NCONS;
                if (idx < WTAP/16)
                    cp_async16(sb + SMEM_W + idx*16, src + idx*16);
            }
            CP_COMMIT();
        }

        int mg = wid & 7;        // M: mg*16
        int ng = wid >> 3;       // N: ng*64
        float acc[8][4];
        #pragma unroll
        for (int ni = 0; ni < 8; ni++)
            #pragma unroll
            for (int r = 0; r < 4; r++) acc[ni][r] = 0.f;

        uint32_t a_off = (uint32_t)((mg*16 + (lane & 15))*RWB + (lane >> 4)*16);
        uint32_t b_off[4];
        #pragma unroll
        for (int q = 0; q < 4; q++)
            b_off[q] = (uint32_t)((ng*64 + q*16 + (lane >> 4)*8 + (lane & 7))*RWB
                                  + ((lane >> 3) & 1)*16);

        #pragma unroll 1
        for (int k = 0; k < 9; k++) {
            int buf = k & 1;
            BAR_SYNC(NB_FULL0 + buf, NTHR);     // A[buf] filled by producers
            CP_WAIT0();                          // W tap k landed

            uint32_t wb = sb + SMEM_W;
            uint32_t ab = sb + (buf ? SMEM_A1 : SMEM_A0);
            #pragma unroll 1
            for (int kk = 0; kk < 8; kk++) {
                uint32_t ka = (uint32_t)(kk*32);
                uint32_t ah[4], al[4], bh[16], bl[16];
                LDSM4(ah[0],ah[1],ah[2],ah[3], ab + a_off + ka);
                LDSM4(al[0],al[1],al[2],al[3], ab + WHALF + a_off + ka);
                #pragma unroll
                for (int q = 0; q < 4; q++) {
                    LDSM4(bh[q*4],bh[q*4+1],bh[q*4+2],bh[q*4+3], wb + b_off[q] + ka);
                    LDSM4(bl[q*4],bl[q*4+1],bl[q*4+2],bl[q*4+3], wb + WHALF + b_off[q] + ka);
                }
                // product hh: 8 independent accs
                #pragma unroll
                for (int ni = 0; ni < 8; ni++)
                    MMA16816(acc[ni], ah[0],ah[1],ah[2],ah[3], bh[ni*2], bh[ni*2+1]);
                // product hl
                #pragma unroll
                for (int ni = 0; ni < 8; ni++)
                    MMA16816(acc[ni], ah[0],ah[1],ah[2],ah[3], bl[ni*2], bl[ni*2+1]);
                // product lh
                #pragma unroll
                for (int ni = 0; ni < 8; ni++)
                    MMA16816(acc[ni], al[0],al[1],al[2],al[3], bh[ni*2], bh[ni*2+1]);
            }

            if (k < 7) BAR_ARRIVE(NB_EMPTY0 + buf, NTHR);   // release A[buf]
            if (k < 8) {
                BAR_SYNC(NB_CONS, NCONS);                   // all consumers done reading W
                const unsigned char* src = g_wsplit + (k+1)*WTAP;
                #pragma unroll
                for (int i = 0; i < 9; i++) {
                    int idx = tid + i*NCONS;
                    if (idx < WTAP/16)
                        cp_async16(sb + SMEM_W + idx*16, src + idx*16);
                }
                CP_COMMIT();
            }
        }

        // ---- epilogue: m16n8 C frag ----
        int g  = lane >> 2;
        int tg = lane & 3;
        int m0 = mg*16 + g;
        int m1 = m0 + 8;
        int ha = h0 + (m0 >> 6), wa = m0 & 63;
        int hb = h0 + (m1 >> 6), wb2 = m1 & 63;
        #pragma unroll
        for (int ni = 0; ni < 8; ni++) {
            int o0 = ng*64 + ni*8 + tg*2;
            int o1 = o0 + 1;
            float b0v = __ldg(&bias[o0]);
            float b1v = __ldg(&bias[o1]);
            out[((b*COUT + o0)*Hn + ha)*Wn + wa]  = acc[ni][0] + b0v;
            out[((b*COUT + o1)*Hn + ha)*Wn + wa]  = acc[ni][1] + b1v;
            out[((b*COUT + o0)*Hn + hb)*Wn + wb2] = acc[ni][2] + b0v;
            out[((b*COUT + o1)*Hn + hb)*Wn + wb2] = acc[ni][3] + b1v;
        }
    } else {
        // ===================== PRODUCER (coalesced) =====================
        int t  = tid - NCONS;               // 0..127
        int g  = t & 7;
        int pg = t >> 3;

        float4 prms[8];
        #pragma unroll
        for (int s = 0; s < 8; s++)
            prms[s] = ((const float4*)g_off)[(blk << 7) + pg*8 + s];

        const float4* xt4 = (const float4*)g_xt;

        #pragma unroll 1
        for (int k = 0; k < 9; k++) {
            int buf = k & 1;
            if (k >= 2) BAR_SYNC(NB_EMPTY0 + buf, NTHR);   // consumers done with A[buf]

            int by = k/3 - 1, bx = k - (k/3)*3 - 1;
            char* abuf = smem + (buf ? SMEM_A1 : SMEM_A0);

            #pragma unroll 1
            for (int s = 0; s < 8; s++) {
                int p  = pg*8 + s;
                int hh = h0 + (p >> 6);
                int wc = p & 63;
                float4 prm = prms[s];
                float sk = (by != 0 && bx != 0) ? prm.z : ((by == 0 && bx == 0) ? 0.f : prm.w);
                float py = (float)hh + (float)by * sk + prm.x;
                float px = (float)wc + (float)bx * sk + prm.y;
                float fy = floorf(py), fx = floorf(px);
                float wy = py - fy,    wx = px - fx;
                int y0 = (int)fy, x0 = (int)fx;
                float cw[4] = {(1.f-wy)*(1.f-wx), (1.f-wy)*wx, wy*(1.f-wx), wy*wx};

                float4 samp[4];
                #pragma unroll
                for (int i = 0; i < 4; i++) samp[i] = make_float4(0.f, 0.f, 0.f, 0.f);

                #pragma unroll
                for (int j = 0; j < 4; j++) {
                    int yc = y0 + (j >> 1);
                    int xc = x0 + (j & 1);
                    if (yc < 0 || yc >= Hn || xc < 0 || xc >= Wn) continue;
                    const float4* src = xt4 + ((b*Hn + yc)*Wn + xc)*(Cn/4);
                    float wj = cw[j];
                    #pragma unroll
                    for (int i = 0; i < 4; i++) {
                        float4 v = src[g + i*8];
                        samp[i].x += wj*v.x; samp[i].y += wj*v.y;
                        samp[i].z += wj*v.z; samp[i].w += wj*v.w;
                    }
                }
                char* ab = abuf + p*RWB;
                #pragma unroll
                for (int i = 0; i < 4; i++) {
                    float4 v = samp[i];
                    __nv_bfloat162 h01 = __floats2bfloat162_rn(v.x, v.y);
                    __nv_bfloat162 h23 = __floats2bfloat162_rn(v.z, v.w);
                    float lx = v.x - __bfloat162float(h01.x);
                    float ly = v.y - __bfloat162float(h01.y);
                    float lz = v.z - __bfloat162float(h23.x);
                    float lw = v.w - __bfloat162float(h23.y);
                    __nv_bfloat162 l01 = __floats2bfloat162_rn(lx, ly);
                    __nv_bfloat162 l23 = __floats2bfloat162_rn(lz, lw);
                    int boff = (g + i*8) * 8;            // byte offset of channel 4*(g+i*8)
                    *(uint2*)(ab + boff)         = make_uint2(*(uint32_t*)&h01, *(uint32_t*)&h23);
                    *(uint2*)(ab + WHALF + boff) = make_uint2(*(uint32_t*)&l01, *(uint32_t*)&l23);
                }
            }
            BAR_ARRIVE(NB_FULL0 + buf, NTHR);   // A[buf] ready
        }
    }
}

// ===========================================================================
extern "C" void kernel_launch(void* const* d_in, const int* in_sizes, int n_in,
                              void* d_out, int out_size) {
    const float* x     = (const float*)d_in[0];
    const float* w_off = (const float*)d_in[1];
    const float* b_off = (const float*)d_in[2];
    const float* w     = (const float*)d_in[3];
    const float* bias  = (const float*)d_in[4];
    float* out = (float*)d_out;

    cudaFuncSetAttribute(main_ws_kernel, cudaFuncAttributeMaxDynamicSharedMemorySize, SMEM_BYTES);

    prep_kernel<<<(9*Cn*COUT + 255)/256, 256>>>(w, w_off);
    transpose_kernel<<<dim3(2, 4, Bn*Hn), dim3(32, 8)>>>(x);
    offset_kernel<<<NPIX/8, 256>>>(b_off);
    main_ws_kernel<<<Bn*Hn/2, NTHR, SMEM_BYTES>>>(bias, out);
}